// round 2
// baseline (speedup 1.0000x reference)
#include <cuda_runtime.h>

#define NN 100000
#define NE 1600000
#define FD 64
#define NG 64
#define EPSV 1e-5f

// -------- scratch (device globals: no allocation allowed) --------
__device__ float g_deg[NN];
__device__ float g_norm[NE];
__device__ float g_h1[NN * FD];
__device__ float g_h2[NN * FD];
__device__ float g_h3[NN * FD];
__device__ float g_out[NN * FD];
__device__ float g_sum[NG * FD];
__device__ float g_sq[NG * FD];
__device__ float g_cnt[NG];
__device__ float g_psum[NG * FD];
__device__ float g_pmax[NG * FD];   // float bits, values >= 0 so uint order == float order
__device__ float g_mc[NG * FD];     // mean * mean_scale
__device__ float g_inv[NG * FD];    // gn_weight * rsqrt(var + eps)

// -------- zero scratch --------
__global__ void k_zero() {
    int i = blockIdx.x * blockDim.x + threadIdx.x;
    if (i < NN * FD) { g_h1[i] = 0.f; g_h2[i] = 0.f; g_h3[i] = 0.f; }
    if (i < NN) g_deg[i] = 0.f;
    if (i < NG * FD) { g_sum[i] = 0.f; g_sq[i] = 0.f; g_psum[i] = 0.f; g_pmax[i] = 0.f; }
    if (i < NG) g_cnt[i] = 0.f;
}

// -------- degree: deg[dst] += ew --------
__global__ void k_deg(const int* __restrict__ dst, const float* __restrict__ ew) {
    int e = blockIdx.x * blockDim.x + threadIdx.x;
    if (e >= NE) return;
    atomicAdd(&g_deg[dst[e]], ew[e]);
}

// -------- norm[e] = dis[src] * ew * dis[dst] --------
__global__ void k_norm(const int* __restrict__ src, const int* __restrict__ dst,
                       const float* __restrict__ ew) {
    int e = blockIdx.x * blockDim.x + threadIdx.x;
    if (e >= NE) return;
    float ds = g_deg[src[e]];
    float dd = g_deg[dst[e]];
    float a = (ds > 0.f) ? rsqrtf(ds) : 0.f;
    float c = (dd > 0.f) ? rsqrtf(dd) : 0.f;
    g_norm[e] = a * ew[e] * c;
}

// -------- weighted scatter: hout[dst] += norm * hin[src], vector red --------
__device__ __forceinline__ void scatter_body(const float* __restrict__ hin,
                                             float* __restrict__ hout,
                                             const int* __restrict__ src,
                                             const int* __restrict__ dst) {
    unsigned tid = blockIdx.x * blockDim.x + threadIdx.x;
    unsigned e = tid >> 4;             // 16 threads per edge (16 float4 chunks)
    if (e >= NE) return;
    int c = (tid & 15) * 4;
    int s = src[e];
    int d = dst[e];
    float w = g_norm[e];
    const float4 v = *(const float4*)(hin + s * FD + c);
    float rx = v.x * w, ry = v.y * w, rz = v.z * w, rw = v.w * w;
    float* p = hout + d * FD + c;
    asm volatile("red.global.add.v4.f32 [%0], {%1,%2,%3,%4};"
                 :: "l"(p), "f"(rx), "f"(ry), "f"(rz), "f"(rw) : "memory");
}

__global__ void k_scat1(const float* __restrict__ x, const int* __restrict__ s,
                        const int* __restrict__ d) { scatter_body(x, g_h1, s, d); }
__global__ void k_scat2(const int* __restrict__ s, const int* __restrict__ d) {
    scatter_body(g_h1, g_h2, s, d);
}
__global__ void k_scat3(const int* __restrict__ s, const int* __restrict__ d) {
    scatter_body(g_h2, g_h3, s, d);
}

// -------- out = x@W0 + h1@W1 + h2@W2 + h3@W3 + b --------
// block = 256 threads = 16 groups x 16 threads; group handles 4 nodes,
// thread j computes output features [4j, 4j+4) for those 4 nodes.
__global__ void k_gemm(const float* __restrict__ x, const float* __restrict__ W,
                       const float* __restrict__ b) {
    __shared__ float Ws[FD * FD];          // one hop matrix at a time (16 KB)
    int grp = threadIdx.x >> 4;
    int j   = threadIdx.x & 15;
    int node0 = blockIdx.x * 64 + grp * 4;

    float4 acc0 = {0,0,0,0}, acc1 = {0,0,0,0}, acc2 = {0,0,0,0}, acc3 = {0,0,0,0};

    // clamped node indices (OOB nodes compute garbage but never store)
    int n0 = min(node0 + 0, NN - 1);
    int n1 = min(node0 + 1, NN - 1);
    int n2 = min(node0 + 2, NN - 1);
    int n3 = min(node0 + 3, NN - 1);

    const float* hs[4] = { x, g_h1, g_h2, g_h3 };

    for (int k = 0; k < 4; k++) {
        for (int t = threadIdx.x; t < FD * FD; t += 256) Ws[t] = W[k * FD * FD + t];
        __syncthreads();
        const float* __restrict__ h = hs[k];
        #pragma unroll
        for (int i = 0; i < FD; i += 4) {
            float4 w0 = *(const float4*)&Ws[(i + 0) * FD + j * 4];
            float4 w1 = *(const float4*)&Ws[(i + 1) * FD + j * 4];
            float4 w2 = *(const float4*)&Ws[(i + 2) * FD + j * 4];
            float4 w3 = *(const float4*)&Ws[(i + 3) * FD + j * 4];
            float4 h0 = *(const float4*)&h[n0 * FD + i];
            float4 h1 = *(const float4*)&h[n1 * FD + i];
            float4 h2 = *(const float4*)&h[n2 * FD + i];
            float4 h3 = *(const float4*)&h[n3 * FD + i];
            acc0.x += h0.x*w0.x + h0.y*w1.x + h0.z*w2.x + h0.w*w3.x;
            acc0.y += h0.x*w0.y + h0.y*w1.y + h0.z*w2.y + h0.w*w3.y;
            acc0.z += h0.x*w0.z + h0.y*w1.z + h0.z*w2.z + h0.w*w3.z;
            acc0.w += h0.x*w0.w + h0.y*w1.w + h0.z*w2.w + h0.w*w3.w;
            acc1.x += h1.x*w0.x + h1.y*w1.x + h1.z*w2.x + h1.w*w3.x;
            acc1.y += h1.x*w0.y + h1.y*w1.y + h1.z*w2.y + h1.w*w3.y;
            acc1.z += h1.x*w0.z + h1.y*w1.z + h1.z*w2.z + h1.w*w3.z;
            acc1.w += h1.x*w0.w + h1.y*w1.w + h1.z*w2.w + h1.w*w3.w;
            acc2.x += h2.x*w0.x + h2.y*w1.x + h2.z*w2.x + h2.w*w3.x;
            acc2.y += h2.x*w0.y + h2.y*w1.y + h2.z*w2.y + h2.w*w3.y;
            acc2.z += h2.x*w0.z + h2.y*w1.z + h2.z*w2.z + h2.w*w3.z;
            acc2.w += h2.x*w0.w + h2.y*w1.w + h2.z*w2.w + h2.w*w3.w;
            acc3.x += h3.x*w0.x + h3.y*w1.x + h3.z*w2.x + h3.w*w3.x;
            acc3.y += h3.x*w0.y + h3.y*w1.y + h3.z*w2.y + h3.w*w3.y;
            acc3.z += h3.x*w0.z + h3.y*w1.z + h3.z*w2.z + h3.w*w3.z;
            acc3.w += h3.x*w0.w + h3.y*w1.w + h3.z*w2.w + h3.w*w3.w;
        }
        __syncthreads();
    }

    float4 bv = *(const float4*)&b[j * 4];
    acc0.x += bv.x; acc0.y += bv.y; acc0.z += bv.z; acc0.w += bv.w;
    acc1.x += bv.x; acc1.y += bv.y; acc1.z += bv.z; acc1.w += bv.w;
    acc2.x += bv.x; acc2.y += bv.y; acc2.z += bv.z; acc2.w += bv.w;
    acc3.x += bv.x; acc3.y += bv.y; acc3.z += bv.z; acc3.w += bv.w;

    if (node0 + 0 < NN) *(float4*)&g_out[(node0 + 0) * FD + j * 4] = acc0;
    if (node0 + 1 < NN) *(float4*)&g_out[(node0 + 1) * FD + j * 4] = acc1;
    if (node0 + 2 < NN) *(float4*)&g_out[(node0 + 2) * FD + j * 4] = acc2;
    if (node0 + 3 < NN) *(float4*)&g_out[(node0 + 3) * FD + j * 4] = acc3;
}

// -------- per-graph sum / sumsq / count over g_out (batch sorted) --------
__global__ void k_stats(const int* __restrict__ batch) {
    int f    = threadIdx.x & 63;
    int lane = threadIdx.x >> 6;   // 0..3
    int base = blockIdx.x * 128;
    float s = 0.f, q = 0.f, c = 0.f;
    int cur = -1;
    for (int t = 0; t < 32; t++) {
        int n = base + t * 4 + lane;
        if (n >= NN) break;
        int g = batch[n];
        if (g != cur) {
            if (cur >= 0) {
                atomicAdd(&g_sum[cur * FD + f], s);
                atomicAdd(&g_sq[cur * FD + f], q);
                if (f == 0) atomicAdd(&g_cnt[cur], c);
            }
            cur = g; s = 0.f; q = 0.f; c = 0.f;
        }
        float v = g_out[n * FD + f];
        s += v; q += v * v; c += 1.f;
    }
    if (cur >= 0) {
        atomicAdd(&g_sum[cur * FD + f], s);
        atomicAdd(&g_sq[cur * FD + f], q);
        if (f == 0) atomicAdd(&g_cnt[cur], c);
    }
}

// -------- mean/var -> premultiplied center & inv-std --------
__global__ void k_meanvar(const float* __restrict__ gnw, const float* __restrict__ ms) {
    int i = blockIdx.x * blockDim.x + threadIdx.x;
    if (i >= NG * FD) return;
    int g = i >> 6, f = i & 63;
    float cnt  = fmaxf(g_cnt[g], 1.f);
    float mean = g_sum[i] / cnt;
    float m    = ms[f];
    // var = E[(out - m*mean)^2] = E[out^2] - 2*m*mean*E[out] + m^2*mean^2
    float var = g_sq[i] / cnt - 2.f * m * mean * mean + m * m * mean * mean;
    g_mc[i]  = mean * m;
    g_inv[i] = gnw[f] * rsqrtf(var + EPSV);
}

// -------- final: h_emb = relu(gn(out) + x), accumulate pool sum/max --------
__global__ void k_final(const float* __restrict__ x, const int* __restrict__ batch,
                        const float* __restrict__ gnb, float* __restrict__ out) {
    int f    = threadIdx.x & 63;
    int lane = threadIdx.x >> 6;
    int base = blockIdx.x * 128;
    float bb = gnb[f];
    float s = 0.f, mx = 0.f, mc = 0.f, iv = 0.f;
    int cur = -1;
    for (int t = 0; t < 32; t++) {
        int n = base + t * 4 + lane;
        if (n >= NN) break;
        int g = batch[n];
        if (g != cur) {
            if (cur >= 0) {
                atomicAdd(&g_psum[cur * FD + f], s);
                atomicMax((unsigned int*)&g_pmax[cur * FD + f], __float_as_uint(mx));
            }
            cur = g; s = 0.f; mx = 0.f;
            mc = g_mc[g * FD + f];
            iv = g_inv[g * FD + f];
        }
        float v = (g_out[n * FD + f] - mc) * iv + bb + x[n * FD + f];
        v = fmaxf(v, 0.f);
        out[n * FD + f] = v;
        s += v;
        mx = fmaxf(mx, v);
    }
    if (cur >= 0) {
        atomicAdd(&g_psum[cur * FD + f], s);
        atomicMax((unsigned int*)&g_pmax[cur * FD + f], __float_as_uint(mx));
    }
}

// -------- pooled output: flat[g] = [mean_pool | max_pool] --------
__global__ void k_pool(float* __restrict__ out) {
    int i = blockIdx.x * blockDim.x + threadIdx.x;
    if (i >= NG * FD) return;
    int g = i >> 6, f = i & 63;
    float cnt = fmaxf(g_cnt[g], 1.f);
    out[NN * FD + g * 2 * FD + f]      = g_psum[i] / cnt;
    out[NN * FD + g * 2 * FD + FD + f] = g_pmax[i];
}

extern "C" void kernel_launch(void* const* d_in, const int* in_sizes, int n_in,
                              void* d_out, int out_size) {
    const float* x     = (const float*)d_in[0];
    const int*   ei    = (const int*)  d_in[1];
    const int*   batch = (const int*)  d_in[2];
    const float* ew    = (const float*)d_in[3];
    const float* W     = (const float*)d_in[4];
    const float* b     = (const float*)d_in[5];
    const float* gnw   = (const float*)d_in[6];
    const float* gnb   = (const float*)d_in[7];
    const float* ms    = (const float*)d_in[8];
    const int* src = ei;
    const int* dst = ei + NE;
    float* out = (float*)d_out;

    k_zero<<<(NN * FD + 255) / 256, 256>>>();
    k_deg<<<(NE + 255) / 256, 256>>>(dst, ew);
    k_norm<<<(NE + 255) / 256, 256>>>(src, dst, ew);
    k_scat1<<<(NE * 16) / 256, 256>>>(x, src, dst);
    k_scat2<<<(NE * 16) / 256, 256>>>(src, dst);
    k_scat3<<<(NE * 16) / 256, 256>>>(src, dst);
    k_gemm<<<(NN + 63) / 64, 256>>>(x, W, b);
    k_stats<<<(NN + 127) / 128, 256>>>(batch);
    k_meanvar<<<(NG * FD + 255) / 256, 256>>>(gnw, ms);
    k_final<<<(NN + 127) / 128, 256>>>(x, batch, gnb, out);
    k_pool<<<(NG * FD + 255) / 256, 256>>>(out);
}